// round 8
// baseline (speedup 1.0000x reference)
#include <cuda_runtime.h>

// ---------------------------------------------------------------------------
// QHashSoftmax: LUT fixed-point softmax, exact-integer reformulation.
//   idx = clamp(rne(x*16), -128, 127) & 255            (cvt.rni.sat.s8)
//   k[idx] = clip(rint(exp(signed(idx)/16 * scale)*128), 0, 127)   (u8 LUT)
//   S = sum(k) over 1024-element row   (exact integer, < 2^18)
//   t = min(floor(S/k), 1023)   (k=0 -> 1023)  [fp32 div+floor exact here]
//   out = min(rint(128/t), 127) / 128           (t=0 -> inf -> 127)
//
// Structure (R7 = R6 + full occupancy):
//  - 4 rows / 256-thread block, thread t handles float4 index t of EACH row
//    (rows at +256): every LDG/STG is per-instruction fully coalesced.
//  - byte-packed codes (pidx/pk u32), dp4a partial sums.
//  - packed-pair redux: rows (0,1)/(2,3) in 16-bit halves (32-lane partials
//    <= 16256, no carry) -> 2 REDUX; 2 packed 64-bit atomics for row sums.
//  - exp table u8[256] = 64 smem words (gather conflict deg <= 2);
//    out table by k: u8[128] = 32 words, one/bank -> conflict-FREE gather.
//  - __launch_bounds__(256,8): reg target 32 -> 8 CTAs/SM, 64 warps resident.
// ---------------------------------------------------------------------------

__device__ unsigned char g_exp_u8[256];   // indexed by wrapped code (q & 255)

__global__ void qhs_setup_kernel(const float* __restrict__ scale_ptr) {
    int i = threadIdx.x;                      // 0..255 = wrapped address
    float scale = *scale_ptr;
    int sv = (i >= 128) ? (i - 256) : i;      // two's-complement decode
    float val = (float)sv * 0.0625f * scale;  // fp32, matches reference
    double e = exp((double)val);              // high-precision exp
    double r = rint(e * 128.0);               // round half to even
    if (r > 127.0) r = 127.0;
    if (r < 0.0)   r = 0.0;
    g_exp_u8[i] = (unsigned char)(int)r;
}

// clamp(round-half-even(f), -128, 127) & 255 in one convert + one mask
__device__ __forceinline__ unsigned qhs_code(float f) {
    int r;
    asm("cvt.rni.sat.s8.f32 %0, %1;" : "=r"(r) : "f"(f));
    return (unsigned)r & 255u;
}

#define ROWS_PER_BLOCK 4

__global__ __launch_bounds__(256, 8) void qhs_main_kernel(
    const float4* __restrict__ x, float4* __restrict__ out)
{
    __shared__ unsigned char sk8[256];                    // exp codes (u8)
    __shared__ unsigned char ocode[ROWS_PER_BLOCK][128];  // out codes by k
    __shared__ unsigned long long sS64[2];                // rows {0,1},{2,3}

    const int tid = threadIdx.x;

    sk8[tid] = g_exp_u8[tid];
    if (tid < 2) sS64[tid] = 0ull;

    // Coalesced: thread t -> float4 index t of each of the block's 4 rows.
    const long long base =
        (long long)blockIdx.x * (ROWS_PER_BLOCK * 256) + tid;

    float4 v0 = __ldcs(&x[base]);
    float4 v1 = __ldcs(&x[base + 256]);
    float4 v2 = __ldcs(&x[base + 512]);
    float4 v3 = __ldcs(&x[base + 768]);

    // Quantize to packed 8-bit codes (independent of tables).
    unsigned pidx[4];
#define QHS_PACK(j, v)                                                  \
    pidx[j] = qhs_code(v.x * 16.0f)          |                          \
              (qhs_code(v.y * 16.0f) << 8)   |                          \
              (qhs_code(v.z * 16.0f) << 16)  |                          \
              (qhs_code(v.w * 16.0f) << 24)
    QHS_PACK(0, v0); QHS_PACK(1, v1); QHS_PACK(2, v2); QHS_PACK(3, v3);
#undef QHS_PACK

    __syncthreads();   // sk8 + sS64 ready

    // ---- Phase 1: gather k bytes, pack, packed-pair redux ---------------
    unsigned pk[4];
    unsigned d[4];
#pragma unroll
    for (int j = 0; j < 4; j++) {
        unsigned p = pidx[j];
        unsigned k0 = sk8[p & 255u];
        unsigned k1 = sk8[(p >> 8) & 255u];
        unsigned k2 = sk8[(p >> 16) & 255u];
        unsigned k3 = sk8[p >> 24];
        pk[j] = k0 | (k1 << 8) | (k2 << 16) | (k3 << 24);
        d[j] = __dp4a(pk[j], 0x01010101u, 0u);     // <= 508
    }
    // rows (0,1) and (2,3) in 16-bit halves; 32-lane sum <= 16256 (no carry)
    unsigned s01 = __reduce_add_sync(0xFFFFFFFFu, d[0] | (d[1] << 16));
    unsigned s23 = __reduce_add_sync(0xFFFFFFFFu, d[2] | (d[3] << 16));
    if ((tid & 31) == 0) {
        // widen 16-bit halves into 32-bit lanes of one 64-bit add each
        atomicAdd(&sS64[0],
                  (unsigned long long)(s01 & 0xFFFFu) |
                  ((unsigned long long)(s01 >> 16) << 32));
        atomicAdd(&sS64[1],
                  (unsigned long long)(s23 & 0xFFFFu) |
                  ((unsigned long long)(s23 >> 16) << 32));
    }

    __syncthreads();   // all sums complete

    // ---- Phase 2: per-row output-code tables (indexed by k) -------------
    // 4 rows x 128 entries = 512; each thread builds 2.
    const unsigned* sS32 = (const unsigned*)sS64;   // [r] = row r sum
#pragma unroll
    for (int e = tid; e < ROWS_PER_BLOCK * 128; e += 256) {
        int rw = e >> 7;
        int kk = e & 127;
        float Sf = (float)sS32[rw];                    // exact (< 2^18)
        // floor(S/k): IEEE div then floor — exact (err 0.0078/k < 1/k gap).
        // kk==0 -> +inf -> clipped to 1023 (reference e==0 branch).
        float t = fminf(floorf(__fdiv_rn(Sf, (float)kk)), 1023.0f);
        // t==0 -> +inf -> clipped to 127 (reference 1/0 saturation).
        float code = fminf(rintf(__fdiv_rn(128.0f, t)), 127.0f);
        ocode[rw][kk] = (unsigned char)(int)code;
    }

    __syncthreads();   // tables ready

    // ---- Phase 3: conflict-free byte gathers + coalesced stores ---------
#pragma unroll
    for (int j = 0; j < 4; j++) {
        unsigned p = pk[j];
        float4 o;
        o.x = (float)ocode[j][p & 255u]         * 0.0078125f;
        o.y = (float)ocode[j][(p >> 8) & 255u]  * 0.0078125f;
        o.z = (float)ocode[j][(p >> 16) & 255u] * 0.0078125f;
        o.w = (float)ocode[j][p >> 24]          * 0.0078125f;
        __stcs(&out[base + j * 256], o);
    }
}

extern "C" void kernel_launch(void* const* d_in, const int* in_sizes, int n_in,
                              void* d_out, int out_size) {
    const float* x     = (const float*)d_in[0];   // [4,12,1024,1024] fp32
    const float* scale = (const float*)d_in[1];   // scalar fp32

    const int n_elems = in_sizes[0];
    const int n_rows  = n_elems >> 10;                   // rows of 1024
    const int n_blocks = n_rows / ROWS_PER_BLOCK;

    qhs_setup_kernel<<<1, 256>>>(scale);
    qhs_main_kernel<<<n_blocks, 256>>>((const float4*)x, (float4*)d_out);
}